// round 9
// baseline (speedup 1.0000x reference)
#include <cuda_runtime.h>
#include <cuda_bf16.h>
#include <math.h>
#include <stdint.h>

#define N_NODES 30000
#define DIM     512
#define NE      300000
#define ET      (NE + N_NODES)     // 330000 edges incl self-loops
#define MPAD    30080              // 235 * 128
#define NPADD   (MPAD * DIM)

// ---------------- scratch (static __device__, no allocations) ----------------
__device__ __nv_bfloat16 g_ah[NPADD];       // A hi (dropout applied)
__device__ __nv_bfloat16 g_al[NPADD];       // A lo
__device__ __nv_bfloat16 g_wh[DIM * DIM];   // W^T hi  [n, k]
__device__ __nv_bfloat16 g_wl[DIM * DIM];   // W^T lo
__device__ float    g_h[NPADD];
__device__ float    g_as[N_NODES];
__device__ float    g_ad[N_NODES];
__device__ float    g_e[ET];
__device__ float    g_ee[ET];               // after fill: masked ee * 2.5
__device__ unsigned g_m[N_NODES];           // encoded float max
__device__ float    g_s[N_NODES];
__device__ int      g_cnt[N_NODES];
__device__ int      g_off[N_NODES + 1];
__device__ int      g_cur[N_NODES];
__device__ int      g_csr[ET];
__device__ double   g_colsum[DIM];
__device__ double   g_sumsq;
__device__ float    g_mu[DIM];
__device__ float    g_inv;

// ---------------- threefry2x32 (JAX-exact, 20 rounds), constexpr-capable ----
__host__ __device__ constexpr unsigned rotl32(unsigned v, int d) {
    return (v << d) | (v >> (32 - d));
}

struct U2 { unsigned a, b; };

__host__ __device__ constexpr U2 threefry2x32(
    unsigned k0, unsigned k1, unsigned c0, unsigned c1)
{
    unsigned ks0 = k0, ks1 = k1, ks2 = k0 ^ k1 ^ 0x1BD11BDAu;
    unsigned x0 = c0 + ks0;
    unsigned x1 = c1 + ks1;

#define TF_R4(a,b,c,d) \
    x0 += x1; x1 = rotl32(x1, a); x1 ^= x0; \
    x0 += x1; x1 = rotl32(x1, b); x1 ^= x0; \
    x0 += x1; x1 = rotl32(x1, c); x1 ^= x0; \
    x0 += x1; x1 = rotl32(x1, d); x1 ^= x0;

    TF_R4(13,15,26,6)   x0 += ks1; x1 += ks2 + 1u;
    TF_R4(17,29,16,24)  x0 += ks2; x1 += ks0 + 2u;
    TF_R4(13,15,26,6)   x0 += ks0; x1 += ks1 + 3u;
    TF_R4(17,29,16,24)  x0 += ks1; x1 += ks2 + 4u;
    TF_R4(13,15,26,6)   x0 += ks2; x1 += ks0 + 5u;
#undef TF_R4
    return U2{x0, x1};
}

constexpr U2 KFEAT = threefry2x32(0u, 42u, 0u, 0u);
constexpr U2 KATT  = threefry2x32(0u, 42u, 0u, 1u);

__device__ __forceinline__ unsigned tf_bits(unsigned k0, unsigned k1, unsigned idx) {
    U2 r = threefry2x32(k0, k1, 0u, idx);
    return r.a ^ r.b;
}

// ---------------- float max encoding for atomicMax ----------------
__device__ __forceinline__ unsigned enc_f(float f) {
    unsigned u = __float_as_uint(f);
    return (u & 0x80000000u) ? ~u : (u | 0x80000000u);
}
__device__ __forceinline__ float dec_f(unsigned k) {
    unsigned u = (k & 0x80000000u) ? (k ^ 0x80000000u) : ~k;
    return __uint_as_float(u);
}

__device__ __forceinline__ uint32_t smem_u32(const void* p) {
    uint32_t a;
    asm("{ .reg .u64 t; cvta.to.shared.u64 t, %1; cvt.u32.u64 %0, t; }"
        : "=r"(a) : "l"(p));
    return a;
}
__device__ __forceinline__ void cp16(uint32_t dst, const void* src) {
    asm volatile("cp.async.cg.shared.global [%0], [%1], 16;"
                 :: "r"(dst), "l"(src) : "memory");
}

// ---------------- kernels ----------------
__global__ void k_init() {
    int i = blockIdx.x * blockDim.x + threadIdx.x;
    if (i < N_NODES) {
        g_cnt[i] = 0; g_s[i] = 0.0f; g_m[i] = 0u;
        g_as[i] = 0.0f; g_ad[i] = 0.0f;
    }
    if (i < DIM)     { g_colsum[i] = 0.0; }
    if (i == 0)      { g_sumsq = 0.0; }
}

// fused feature-dropout + bf16 hi/lo split, 4 elems/thread (ILP on threefry)
// processes elements [ebase, ebase + ecnt)
__global__ void k_prep_a(const float* __restrict__ x, unsigned ebase, unsigned ecnt) {
    unsigned t  = blockIdx.x * blockDim.x + threadIdx.x;
    unsigned i0 = ebase + t * 4;
    if (t * 4 >= ecnt || i0 >= (unsigned)NPADD) return;

    unsigned hh[2] = {0u, 0u}, ll[2] = {0u, 0u};
    if (i0 < (unsigned)(N_NODES * DIM)) {       // region is 4-divisible
        float4 xv = *(const float4*)(x + i0);
        float vs[4] = {xv.x, xv.y, xv.z, xv.w};
        unsigned mb[4];
#pragma unroll
        for (int j = 0; j < 4; j++) mb[j] = tf_bits(KFEAT.a, KFEAT.b, i0 + j);
#pragma unroll
        for (int j = 0; j < 4; j++) {
            // keep  <=>  u < 0.5  <=>  top bit of bits is 0
            float v = (mb[j] & 0x80000000u) ? 0.0f : vs[j] * 2.0f;
            __nv_bfloat16 h = __float2bfloat16(v);
            __nv_bfloat16 l = __float2bfloat16(v - __bfloat162float(h));
            unsigned hu = (unsigned)__bfloat16_as_ushort(h);
            unsigned lu = (unsigned)__bfloat16_as_ushort(l);
            hh[j >> 1] |= hu << ((j & 1) * 16);
            ll[j >> 1] |= lu << ((j & 1) * 16);
        }
    }
    *(uint2*)((unsigned short*)g_ah + i0) = make_uint2(hh[0], hh[1]);
    *(uint2*)((unsigned short*)g_al + i0) = make_uint2(ll[0], ll[1]);
}

// transpose + bf16 hi/lo split of W:  g_w*[n*512+k] = split(W[k*512+n])
__global__ void k_prep_w(const float* __restrict__ W) {
    int i = blockIdx.x * blockDim.x + threadIdx.x;
    if (i >= DIM * DIM) return;
    int n = i >> 9, k = i & (DIM - 1);
    float v = W[k * DIM + n];
    __nv_bfloat16 h = __float2bfloat16(v);
    g_wh[i] = h;
    g_wl[i] = __float2bfloat16(v - __bfloat162float(h));
}

// ---------------- mma.sync bf16 GEMM, 4-stage cp.async pipeline ------------
// CTA tile 128x128, 8 warps (2x4), warp tile 64x32, BK=32.
// Fused epilogue: h row-dots with att_src/att_dst -> g_as/g_ad (atomic).
#define LDT 40                      // padded smem lead dim (bf16 elems)
#define GBK 32
#define NCH (DIM / GBK)             // 16 chunks per pass
#define NQ  (3 * NCH)               // 48 chunk-iterations (3 passes)
#define STAGE_B (128 * LDT * 2)     // 10240 B per tile buffer
#define NSTG 4
#define SM_GEMM (2 * NSTG * STAGE_B) // 81920 B

__global__ void __launch_bounds__(256, 2) k_gemm_mma(
    const float* __restrict__ att_src,
    const float* __restrict__ att_dst,
    int rowtile0)
{
    extern __shared__ char smem[];
    __nv_bfloat16* Asm = (__nv_bfloat16*)smem;                    // 4 stages
    __nv_bfloat16* Bsm = (__nv_bfloat16*)(smem + NSTG * STAGE_B); // 4 stages

    const int tid  = threadIdx.x;
    const int wid  = tid >> 5;
    const int lane = tid & 31;
    const int brow = (rowtile0 + blockIdx.y) * 128;
    const int bcol = blockIdx.x * 128;
    const int wm   = (wid >> 2) * 64;
    const int wn   = (wid & 3) * 32;

    const int lr = tid >> 2;              // 0..63 (x2 -> 128 rows)
    const int lc = (tid & 3) * 8;         // bf16 col group

    const uint32_t a_smem0 = smem_u32(Asm);
    const uint32_t b_smem0 = smem_u32(Bsm);

    float acc[4][4][4];
#pragma unroll
    for (int mt = 0; mt < 4; mt++)
#pragma unroll
        for (int nt = 0; nt < 4; nt++)
#pragma unroll
            for (int c = 0; c < 4; c++) acc[mt][nt][c] = 0.0f;

    const int a_row  = wm + (lane & 15);
    const int a_koff = (lane >> 4) * 8;
    const int b_row  = wn + (lane & 15);

    auto load_chunk = [&](int q, int st) {
        int pass = q >> 4;                 // 0: Ah*Wh 1: Ah*Wl 2: Al*Wh
        int k0   = (q & 15) * GBK;
        const __nv_bfloat16* __restrict__ Ap = (pass == 2) ? g_al : g_ah;
        const __nv_bfloat16* __restrict__ Bp = (pass == 1) ? g_wl : g_wh;
        uint32_t ab = a_smem0 + st * STAGE_B;
        uint32_t bb = b_smem0 + st * STAGE_B;
#pragma unroll
        for (int it = 0; it < 2; it++) {
            int r = lr + it * 64;
            cp16(ab + (r * LDT + lc) * 2, Ap + (size_t)(brow + r) * DIM + k0 + lc);
            cp16(bb + (r * LDT + lc) * 2, Bp + (size_t)(bcol + r) * DIM + k0 + lc);
        }
    };

    load_chunk(0, 0);
    asm volatile("cp.async.commit_group;" ::: "memory");
    load_chunk(1, 1);
    asm volatile("cp.async.commit_group;" ::: "memory");
    load_chunk(2, 2);
    asm volatile("cp.async.commit_group;" ::: "memory");

    for (int q = 0; q < NQ; q++) {
        int st = q & 3;
        asm volatile("cp.async.wait_group 2;" ::: "memory");
        __syncthreads();
        if (q + 3 < NQ) load_chunk(q + 3, (q + 3) & 3);
        asm volatile("cp.async.commit_group;" ::: "memory");

        const __nv_bfloat16* As = Asm + st * (128 * LDT);
        const __nv_bfloat16* Bs = Bsm + st * (128 * LDT);
#pragma unroll
        for (int ks = 0; ks < 2; ks++) {
            int k16 = ks * 16;
            uint32_t a[4][4];
#pragma unroll
            for (int mt = 0; mt < 4; mt++) {
                uint32_t addr = smem_u32(
                    &As[(a_row + mt * 16) * LDT + k16 + a_koff]);
                asm volatile(
                    "ldmatrix.sync.aligned.m8n8.x4.shared.b16 {%0,%1,%2,%3}, [%4];"
                    : "=r"(a[mt][0]), "=r"(a[mt][1]), "=r"(a[mt][2]), "=r"(a[mt][3])
                    : "r"(addr));
            }
            uint32_t b[4][2];
#pragma unroll
            for (int nt2 = 0; nt2 < 2; nt2++) {
                uint32_t addr = smem_u32(
                    &Bs[(b_row + nt2 * 16) * LDT + k16 + a_koff]);
                uint32_t r0, r1, r2, r3;
                asm volatile(
                    "ldmatrix.sync.aligned.m8n8.x4.shared.b16 {%0,%1,%2,%3}, [%4];"
                    : "=r"(r0), "=r"(r1), "=r"(r2), "=r"(r3)
                    : "r"(addr));
                b[2 * nt2][0] = r0; b[2 * nt2 + 1][0] = r1;
                b[2 * nt2][1] = r2; b[2 * nt2 + 1][1] = r3;
            }
#pragma unroll
            for (int mt = 0; mt < 4; mt++)
#pragma unroll
                for (int nt = 0; nt < 4; nt++) {
                    asm volatile(
                        "mma.sync.aligned.m16n8k16.row.col.f32.bf16.bf16.f32 "
                        "{%0,%1,%2,%3}, {%4,%5,%6,%7}, {%8,%9}, {%0,%1,%2,%3};"
                        : "+f"(acc[mt][nt][0]), "+f"(acc[mt][nt][1]),
                          "+f"(acc[mt][nt][2]), "+f"(acc[mt][nt][3])
                        : "r"(a[mt][0]), "r"(a[mt][1]), "r"(a[mt][2]), "r"(a[mt][3]),
                          "r"(b[nt][0]), "r"(b[nt][1]));
                }
        }
    }

    // epilogue: write fp32 result + fused att dot products
    const int group = lane >> 2;
    const int tg    = lane & 3;

    float as0[4], as1[4], ad0[4], ad1[4];
#pragma unroll
    for (int nt = 0; nt < 4; nt++) {
        int col = bcol + wn + nt * 8 + tg * 2;
        as0[nt] = att_src[col];  as1[nt] = att_src[col + 1];
        ad0[nt] = att_dst[col];  ad1[nt] = att_dst[col + 1];
    }

#pragma unroll
    for (int mt = 0; mt < 4; mt++) {
        int m0 = brow + wm + mt * 16 + group;
        float v0s = 0.f, v8s = 0.f, v0d = 0.f, v8d = 0.f;
#pragma unroll
        for (int nt = 0; nt < 4; nt++) {
            int col = bcol + wn + nt * 8 + tg * 2;
            *(float2*)(g_h + (size_t)m0 * DIM + col) =
                make_float2(acc[mt][nt][0], acc[mt][nt][1]);
            *(float2*)(g_h + (size_t)(m0 + 8) * DIM + col) =
                make_float2(acc[mt][nt][2], acc[mt][nt][3]);
            v0s += acc[mt][nt][0] * as0[nt] + acc[mt][nt][1] * as1[nt];
            v8s += acc[mt][nt][2] * as0[nt] + acc[mt][nt][3] * as1[nt];
            v0d += acc[mt][nt][0] * ad0[nt] + acc[mt][nt][1] * ad1[nt];
            v8d += acc[mt][nt][2] * ad0[nt] + acc[mt][nt][3] * ad1[nt];
        }
#pragma unroll
        for (int o = 1; o <= 2; o <<= 1) {
            v0s += __shfl_xor_sync(0xffffffffu, v0s, o);
            v8s += __shfl_xor_sync(0xffffffffu, v8s, o);
            v0d += __shfl_xor_sync(0xffffffffu, v0d, o);
            v8d += __shfl_xor_sync(0xffffffffu, v8d, o);
        }
        if (tg == 0) {
            if (m0 < N_NODES) {
                atomicAdd(&g_as[m0], v0s);
                atomicAdd(&g_ad[m0], v0d);
            }
            if (m0 + 8 < N_NODES) {
                atomicAdd(&g_as[m0 + 8], v8s);
                atomicAdd(&g_ad[m0 + 8], v8d);
            }
        }
    }
}

__global__ void k_edge(const int* __restrict__ ei) {
    int j = blockIdx.x * blockDim.x + threadIdx.x;
    if (j >= ET) return;
    int src = (j < NE) ? ei[j]      : (j - NE);
    int dst = (j < NE) ? ei[NE + j] : (j - NE);
    float e = g_as[src] + g_ad[dst];
    e = (e >= 0.0f) ? e : 0.2f * e;                 // LeakyReLU(0.2)
    g_e[j] = e;
    atomicMax(&g_m[dst], enc_f(e));
    atomicAdd(&g_cnt[dst], 1);
}

__global__ void k_scan() {
    __shared__ int sh[1024];
    int tid = threadIdx.x;
    int carry = 0;
    for (int base = 0; base < N_NODES; base += 1024) {
        int i = base + tid;
        int v = (i < N_NODES) ? g_cnt[i] : 0;
        sh[tid] = v;
        __syncthreads();
        for (int ofs = 1; ofs < 1024; ofs <<= 1) {
            int t = (tid >= ofs) ? sh[tid - ofs] : 0;
            __syncthreads();
            sh[tid] += t;
            __syncthreads();
        }
        int incl = sh[tid];
        if (i < N_NODES) {
            int ex = carry + incl - v;
            g_off[i] = ex;
            g_cur[i] = ex;
        }
        carry += sh[1023];
        __syncthreads();
    }
    if (tid == 0) g_off[N_NODES] = carry;
}

// softmax numerators + CSR fill + attention dropout (threefry once per edge)
__global__ void k_fill(const int* __restrict__ ei) {
    int j = blockIdx.x * blockDim.x + threadIdx.x;
    if (j >= ET) return;
    int dst = (j < NE) ? ei[NE + j] : (j - NE);
    float m  = dec_f(g_m[dst]);
    float ee = expf(g_e[j] - m);
    atomicAdd(&g_s[dst], ee);
    int pos = atomicAdd(&g_cur[dst], 1);
    g_csr[pos] = j;
    unsigned bits = tf_bits(KATT.a, KATT.b, (unsigned)j);
    float u = __uint_as_float((bits >> 9) | 0x3f800000u) - 1.0f;
    g_ee[j] = (u < 0.4f) ? ee * 2.5f : 0.0f;        // keep prob 0.4, x1/0.4
}

// block per dst node; 128 threads x float4 = 512 cols
__global__ void __launch_bounds__(128) k_agg(
    const int* __restrict__ ei,
    const float* __restrict__ bias,
    float* __restrict__ out)
{
    int dst = blockIdx.x;
    int c   = threadIdx.x * 4;
    float inv = 1.0f / (g_s[dst] + 1e-16f);
    float4 acc = make_float4(0.f, 0.f, 0.f, 0.f);
    int beg = g_off[dst], end = g_off[dst + 1];
    for (int p = beg; p < end; p++) {
        int eid = g_csr[p];
        float a = g_ee[eid];
        if (a != 0.0f) {
            float w = a * inv;
            int src = (eid < NE) ? ei[eid] : (eid - NE);
            float4 hv = *(const float4*)(g_h + (size_t)src * DIM + c);
            acc.x = fmaf(w, hv.x, acc.x);
            acc.y = fmaf(w, hv.y, acc.y);
            acc.z = fmaf(w, hv.z, acc.z);
            acc.w = fmaf(w, hv.w, acc.w);
        }
    }
    float4 bv = *(const float4*)(bias + c);
    acc.x += bv.x; acc.y += bv.y; acc.z += bv.z; acc.w += bv.w;
    *(float4*)(out + (size_t)dst * DIM + c) = acc;
}

// column sums + total sum of squares (for PairNorm)
#define CM_ROWS 235
__global__ void __launch_bounds__(256) k_colmean(const float* __restrict__ out) {
    __shared__ double ssq_sh[256];
    int tid = threadIdx.x;
    int r0 = blockIdx.x * CM_ROWS;
    int r1 = min(N_NODES, r0 + CM_ROWS);
    float s1 = 0.0f, s2 = 0.0f;
    double ssq = 0.0;
    for (int r = r0; r < r1; r++) {
        float v1 = out[(size_t)r * DIM + tid];
        float v2 = out[(size_t)r * DIM + tid + 256];
        s1 += v1; s2 += v2;
        ssq += (double)v1 * v1 + (double)v2 * v2;
    }
    atomicAdd(&g_colsum[tid],       (double)s1);
    atomicAdd(&g_colsum[tid + 256], (double)s2);
    ssq_sh[tid] = ssq;
    __syncthreads();
    for (int o = 128; o > 0; o >>= 1) {
        if (tid < o) ssq_sh[tid] += ssq_sh[tid + o];
        __syncthreads();
    }
    if (tid == 0) atomicAdd(&g_sumsq, ssq_sh[0]);
}

__global__ void k_stats() {
    __shared__ double sh[512];
    int t = threadIdx.x;
    double mu = g_colsum[t] / (double)N_NODES;
    g_mu[t] = (float)mu;
    sh[t] = mu * mu;
    __syncthreads();
    for (int o = 256; o > 0; o >>= 1) {
        if (t < o) sh[t] += sh[t + o];
        __syncthreads();
    }
    if (t == 0) {
        double var = g_sumsq / (double)N_NODES - sh[0];
        g_inv = (float)(1.0 / sqrt(1e-6 + var));
    }
}

__global__ void k_final(float* __restrict__ out) {
    unsigned i = (blockIdx.x * blockDim.x + threadIdx.x) * 4;
    if (i >= (unsigned)(N_NODES * DIM)) return;
    float4 v  = *(const float4*)(out + i);
    float4 mu = *(const float4*)(g_mu + (i & (DIM - 1)));
    float inv = g_inv;
    v.x = fmaxf((v.x - mu.x) * inv, 0.0f);
    v.y = fmaxf((v.y - mu.y) * inv, 0.0f);
    v.z = fmaxf((v.z - mu.z) * inv, 0.0f);
    v.w = fmaxf((v.w - mu.w) * inv, 0.0f);
    *(float4*)(out + i) = v;
}

// ---------------- aux stream/events (created once, outside graph capture) ---
struct Aux {
    cudaStream_t s2;
    cudaEvent_t  evF;
    cudaEvent_t  ev[4];
    Aux() {
        cudaStreamCreateWithFlags(&s2, cudaStreamNonBlocking);
        cudaEventCreateWithFlags(&evF, cudaEventDisableTiming);
        for (int i = 0; i < 4; i++)
            cudaEventCreateWithFlags(&ev[i], cudaEventDisableTiming);
    }
};
static Aux& aux() { static Aux a; return a; }

// ---------------- launch ----------------
extern "C" void kernel_launch(void* const* d_in, const int* in_sizes, int n_in,
                              void* d_out, int out_size)
{
    const float* x       = (const float*)d_in[0];
    const int*   ei      = (const int*)  d_in[1];
    const float* W       = (const float*)d_in[2];
    const float* att_src = (const float*)d_in[3];
    const float* att_dst = (const float*)d_in[4];
    const float* bias    = (const float*)d_in[5];
    float*       out     = (float*)d_out;
    (void)in_sizes; (void)n_in; (void)out_size;

    cudaFuncSetAttribute(k_gemm_mma,
                         cudaFuncAttributeMaxDynamicSharedMemorySize, SM_GEMM);

    Aux& A = aux();

    // chunking: 235 row-tiles -> 59,59,59,58
    const int tile0[4] = {0, 59, 118, 177};
    const int ntile[4] = {59, 59, 59, 58};

    k_init<<<(N_NODES + 255) / 256, 256>>>();
    k_prep_w<<<(DIM * DIM + 255) / 256, 256>>>(W);

    // fork: prep_a chunks on s2
    cudaEventRecord(A.evF, 0);
    cudaStreamWaitEvent(A.s2, A.evF, 0);
    for (int c = 0; c < 4; c++) {
        unsigned ebase = (unsigned)tile0[c] * 128u * DIM;
        unsigned ecnt  = (unsigned)ntile[c] * 128u * DIM;
        k_prep_a<<<(ecnt / 4 + 255) / 256, 256, 0, A.s2>>>(x, ebase, ecnt);
        cudaEventRecord(A.ev[c], A.s2);
    }

    // GEMM per chunk on default stream, gated by chunk events
    for (int c = 0; c < 4; c++) {
        cudaStreamWaitEvent(0, A.ev[c], 0);
        k_gemm_mma<<<dim3(4, ntile[c]), 256, SM_GEMM>>>(att_src, att_dst, tile0[c]);
    }

    k_edge<<<(ET + 255) / 256, 256>>>(ei);
    k_scan<<<1, 1024>>>();
    k_fill<<<(ET + 255) / 256, 256>>>(ei);
    k_agg<<<N_NODES, 128>>>(ei, bias, out);
    k_colmean<<<(N_NODES + CM_ROWS - 1) / CM_ROWS, 256>>>(out);
    k_stats<<<1, 512>>>();
    k_final<<<(N_NODES * DIM / 4 + 255) / 256, 256>>>(out);
}

// round 10
// speedup vs baseline: 1.1031x; 1.1031x over previous
#include <cuda_runtime.h>
#include <cuda_bf16.h>
#include <math.h>
#include <stdint.h>

#define N_NODES 30000
#define DIM     512
#define NE      300000
#define ET      (NE + N_NODES)     // 330000 edges incl self-loops
#define MPAD    30080              // 235 * 128
#define NPADD   (MPAD * DIM)

// ---------------- scratch (static __device__, no allocations) ----------------
__device__ __nv_bfloat16 g_ah[NPADD];       // A hi (dropout applied)
__device__ __nv_bfloat16 g_al[NPADD];       // A lo
__device__ __nv_bfloat16 g_wh[DIM * DIM];   // W^T hi  [n, k]
__device__ __nv_bfloat16 g_wl[DIM * DIM];   // W^T lo
__device__ float    g_h[NPADD];
__device__ float    g_as[N_NODES];
__device__ float    g_ad[N_NODES];
__device__ float    g_e[ET];
__device__ float    g_ee[ET];               // after fill: masked ee * 2.5
__device__ unsigned g_m[N_NODES];           // encoded float max
__device__ float    g_s[N_NODES];
__device__ int      g_cnt[N_NODES];
__device__ int      g_off[N_NODES + 1];
__device__ int      g_cur[N_NODES];
__device__ int      g_csr[ET];
__device__ double   g_colsum[DIM];
__device__ double   g_sumsq;
__device__ float    g_mu[DIM];
__device__ float    g_inv;

// ---------------- threefry2x32 (JAX-exact, 20 rounds), constexpr-capable ----
__host__ __device__ constexpr unsigned rotl32(unsigned v, int d) {
    return (v << d) | (v >> (32 - d));
}

struct U2 { unsigned a, b; };

__host__ __device__ constexpr U2 threefry2x32(
    unsigned k0, unsigned k1, unsigned c0, unsigned c1)
{
    unsigned ks0 = k0, ks1 = k1, ks2 = k0 ^ k1 ^ 0x1BD11BDAu;
    unsigned x0 = c0 + ks0;
    unsigned x1 = c1 + ks1;

#define TF_R4(a,b,c,d) \
    x0 += x1; x1 = rotl32(x1, a); x1 ^= x0; \
    x0 += x1; x1 = rotl32(x1, b); x1 ^= x0; \
    x0 += x1; x1 = rotl32(x1, c); x1 ^= x0; \
    x0 += x1; x1 = rotl32(x1, d); x1 ^= x0;

    TF_R4(13,15,26,6)   x0 += ks1; x1 += ks2 + 1u;
    TF_R4(17,29,16,24)  x0 += ks2; x1 += ks0 + 2u;
    TF_R4(13,15,26,6)   x0 += ks0; x1 += ks1 + 3u;
    TF_R4(17,29,16,24)  x0 += ks1; x1 += ks2 + 4u;
    TF_R4(13,15,26,6)   x0 += ks2; x1 += ks0 + 5u;
#undef TF_R4
    return U2{x0, x1};
}

constexpr U2 KFEAT = threefry2x32(0u, 42u, 0u, 0u);
constexpr U2 KATT  = threefry2x32(0u, 42u, 0u, 1u);

__device__ __forceinline__ unsigned tf_bits(unsigned k0, unsigned k1, unsigned idx) {
    U2 r = threefry2x32(k0, k1, 0u, idx);
    return r.a ^ r.b;
}

// ---------------- float max encoding for atomicMax ----------------
__device__ __forceinline__ unsigned enc_f(float f) {
    unsigned u = __float_as_uint(f);
    return (u & 0x80000000u) ? ~u : (u | 0x80000000u);
}
__device__ __forceinline__ float dec_f(unsigned k) {
    unsigned u = (k & 0x80000000u) ? (k ^ 0x80000000u) : ~k;
    return __uint_as_float(u);
}

__device__ __forceinline__ uint32_t smem_u32(const void* p) {
    uint32_t a;
    asm("{ .reg .u64 t; cvta.to.shared.u64 t, %1; cvt.u32.u64 %0, t; }"
        : "=r"(a) : "l"(p));
    return a;
}
__device__ __forceinline__ void cp16(uint32_t dst, const void* src) {
    asm volatile("cp.async.cg.shared.global [%0], [%1], 16;"
                 :: "r"(dst), "l"(src) : "memory");
}

// ---------------- kernels ----------------
__global__ void k_init() {
    int i = blockIdx.x * blockDim.x + threadIdx.x;
    if (i < N_NODES) {
        g_cnt[i] = 0; g_s[i] = 0.0f; g_m[i] = 0u;
        g_as[i] = 0.0f; g_ad[i] = 0.0f;
    }
    if (i < DIM)     { g_colsum[i] = 0.0; }
    if (i == 0)      { g_sumsq = 0.0; }
}

// fused feature-dropout + bf16 hi/lo split, 4 elems/thread (ILP on threefry)
__global__ void k_prep_a(const float* __restrict__ x) {
    unsigned t  = blockIdx.x * blockDim.x + threadIdx.x;
    unsigned i0 = t * 4;
    if (i0 >= (unsigned)NPADD) return;

    unsigned hh[2] = {0u, 0u}, ll[2] = {0u, 0u};
    if (i0 < (unsigned)(N_NODES * DIM)) {       // region is 4-divisible
        float4 xv = *(const float4*)(x + i0);
        float vs[4] = {xv.x, xv.y, xv.z, xv.w};
        unsigned mb[4];
#pragma unroll
        for (int j = 0; j < 4; j++) mb[j] = tf_bits(KFEAT.a, KFEAT.b, i0 + j);
#pragma unroll
        for (int j = 0; j < 4; j++) {
            // keep  <=>  u < 0.5  <=>  top bit of bits is 0
            float v = (mb[j] & 0x80000000u) ? 0.0f : vs[j] * 2.0f;
            __nv_bfloat16 h = __float2bfloat16(v);
            __nv_bfloat16 l = __float2bfloat16(v - __bfloat162float(h));
            unsigned hu = (unsigned)__bfloat16_as_ushort(h);
            unsigned lu = (unsigned)__bfloat16_as_ushort(l);
            hh[j >> 1] |= hu << ((j & 1) * 16);
            ll[j >> 1] |= lu << ((j & 1) * 16);
        }
    }
    *(uint2*)((unsigned short*)g_ah + i0) = make_uint2(hh[0], hh[1]);
    *(uint2*)((unsigned short*)g_al + i0) = make_uint2(ll[0], ll[1]);
}

// transpose + bf16 hi/lo split of W:  g_w*[n*512+k] = split(W[k*512+n])
__global__ void k_prep_w(const float* __restrict__ W) {
    int i = blockIdx.x * blockDim.x + threadIdx.x;
    if (i >= DIM * DIM) return;
    int n = i >> 9, k = i & (DIM - 1);
    float v = W[k * DIM + n];
    __nv_bfloat16 h = __float2bfloat16(v);
    g_wh[i] = h;
    g_wl[i] = __float2bfloat16(v - __bfloat162float(h));
}

// ---------------- mma.sync bf16 GEMM, single-loop 3-product -----------------
// CTA tile 128x128, 8 warps (2x4), warp tile 64x32, BK=32.
// Per K-chunk load Ah,Al,Wh,Wl once; acc += ah*wh + ah*wl + al*wh.
// Fused epilogue: h row-dots with att_src/att_dst -> g_as/g_ad (atomic).
#define LDT 40                      // padded smem lead dim (bf16 elems)
#define GBK 32
#define NCH (DIM / GBK)             // 16 chunks
#define TILE_B (128 * LDT * 2)      // 10240 B per tile
#define STG_B  (4 * TILE_B)         // Ah,Al,Bh,Bl per stage = 40960 B
#define SM_GEMM (2 * STG_B)         // 81920 B

__global__ void __launch_bounds__(256, 2) k_gemm_mma(
    const float* __restrict__ att_src,
    const float* __restrict__ att_dst)
{
    extern __shared__ char smem[];

    const int tid  = threadIdx.x;
    const int wid  = tid >> 5;
    const int lane = tid & 31;
    const int brow = blockIdx.y * 128;
    const int bcol = blockIdx.x * 128;
    const int wm   = (wid >> 2) * 64;
    const int wn   = (wid & 3) * 32;

    const int lr = tid >> 2;              // 0..63 (x2 -> 128 rows)
    const int lc = (tid & 3) * 8;         // bf16 col group

    const uint32_t s0 = smem_u32(smem);

    float acc[4][4][4];
#pragma unroll
    for (int mt = 0; mt < 4; mt++)
#pragma unroll
        for (int nt = 0; nt < 4; nt++)
#pragma unroll
            for (int c = 0; c < 4; c++) acc[mt][nt][c] = 0.0f;

    const int a_row  = wm + (lane & 15);
    const int a_koff = (lane >> 4) * 8;
    const int b_row  = wn + (lane & 15);

    auto load_chunk = [&](int c, int st) {
        int k0 = c * GBK;
        uint32_t base = s0 + st * STG_B;
#pragma unroll
        for (int it = 0; it < 2; it++) {
            int r = lr + it * 64;
            uint32_t off = (r * LDT + lc) * 2;
            size_t ga = (size_t)(brow + r) * DIM + k0 + lc;
            size_t gb = (size_t)(bcol + r) * DIM + k0 + lc;
            cp16(base + 0 * TILE_B + off, g_ah + ga);
            cp16(base + 1 * TILE_B + off, g_al + ga);
            cp16(base + 2 * TILE_B + off, g_wh + gb);
            cp16(base + 3 * TILE_B + off, g_wl + gb);
        }
    };

    load_chunk(0, 0);
    asm volatile("cp.async.commit_group;" ::: "memory");

    for (int c = 0; c < NCH; c++) {
        int st = c & 1;
        if (c + 1 < NCH) {
            load_chunk(c + 1, st ^ 1);
            asm volatile("cp.async.commit_group;" ::: "memory");
            asm volatile("cp.async.wait_group 1;" ::: "memory");
        } else {
            asm volatile("cp.async.wait_group 0;" ::: "memory");
        }
        __syncthreads();

        const __nv_bfloat16* Ah = (const __nv_bfloat16*)(smem + st * STG_B);
        const __nv_bfloat16* Al = (const __nv_bfloat16*)(smem + st * STG_B + TILE_B);
        const __nv_bfloat16* Bh = (const __nv_bfloat16*)(smem + st * STG_B + 2 * TILE_B);
        const __nv_bfloat16* Bl = (const __nv_bfloat16*)(smem + st * STG_B + 3 * TILE_B);

#pragma unroll
        for (int ks = 0; ks < 2; ks++) {
            int k16 = ks * 16;
            // B operands (resident for the whole k16 slice)
            uint32_t bh[4][2], bl[4][2];
#pragma unroll
            for (int nt2 = 0; nt2 < 2; nt2++) {
                uint32_t r0, r1, r2, r3;
                uint32_t addr = smem_u32(&Bh[(b_row + nt2 * 16) * LDT + k16 + a_koff]);
                asm volatile(
                    "ldmatrix.sync.aligned.m8n8.x4.shared.b16 {%0,%1,%2,%3}, [%4];"
                    : "=r"(r0), "=r"(r1), "=r"(r2), "=r"(r3) : "r"(addr));
                bh[2 * nt2][0] = r0; bh[2 * nt2 + 1][0] = r1;
                bh[2 * nt2][1] = r2; bh[2 * nt2 + 1][1] = r3;
                addr = smem_u32(&Bl[(b_row + nt2 * 16) * LDT + k16 + a_koff]);
                asm volatile(
                    "ldmatrix.sync.aligned.m8n8.x4.shared.b16 {%0,%1,%2,%3}, [%4];"
                    : "=r"(r0), "=r"(r1), "=r"(r2), "=r"(r3) : "r"(addr));
                bl[2 * nt2][0] = r0; bl[2 * nt2 + 1][0] = r1;
                bl[2 * nt2][1] = r2; bl[2 * nt2 + 1][1] = r3;
            }
            // A-high: two products
            uint32_t a[4][4];
#pragma unroll
            for (int mt = 0; mt < 4; mt++) {
                uint32_t addr = smem_u32(&Ah[(a_row + mt * 16) * LDT + k16 + a_koff]);
                asm volatile(
                    "ldmatrix.sync.aligned.m8n8.x4.shared.b16 {%0,%1,%2,%3}, [%4];"
                    : "=r"(a[mt][0]), "=r"(a[mt][1]), "=r"(a[mt][2]), "=r"(a[mt][3])
                    : "r"(addr));
            }
#pragma unroll
            for (int mt = 0; mt < 4; mt++)
#pragma unroll
                for (int nt = 0; nt < 4; nt++) {
                    asm volatile(
                        "mma.sync.aligned.m16n8k16.row.col.f32.bf16.bf16.f32 "
                        "{%0,%1,%2,%3}, {%4,%5,%6,%7}, {%8,%9}, {%0,%1,%2,%3};"
                        : "+f"(acc[mt][nt][0]), "+f"(acc[mt][nt][1]),
                          "+f"(acc[mt][nt][2]), "+f"(acc[mt][nt][3])
                        : "r"(a[mt][0]), "r"(a[mt][1]), "r"(a[mt][2]), "r"(a[mt][3]),
                          "r"(bh[nt][0]), "r"(bh[nt][1]));
                    asm volatile(
                        "mma.sync.aligned.m16n8k16.row.col.f32.bf16.bf16.f32 "
                        "{%0,%1,%2,%3}, {%4,%5,%6,%7}, {%8,%9}, {%0,%1,%2,%3};"
                        : "+f"(acc[mt][nt][0]), "+f"(acc[mt][nt][1]),
                          "+f"(acc[mt][nt][2]), "+f"(acc[mt][nt][3])
                        : "r"(a[mt][0]), "r"(a[mt][1]), "r"(a[mt][2]), "r"(a[mt][3]),
                          "r"(bl[nt][0]), "r"(bl[nt][1]));
                }
            // A-low: one product (reuse a regs)
#pragma unroll
            for (int mt = 0; mt < 4; mt++) {
                uint32_t addr = smem_u32(&Al[(a_row + mt * 16) * LDT + k16 + a_koff]);
                asm volatile(
                    "ldmatrix.sync.aligned.m8n8.x4.shared.b16 {%0,%1,%2,%3}, [%4];"
                    : "=r"(a[mt][0]), "=r"(a[mt][1]), "=r"(a[mt][2]), "=r"(a[mt][3])
                    : "r"(addr));
            }
#pragma unroll
            for (int mt = 0; mt < 4; mt++)
#pragma unroll
                for (int nt = 0; nt < 4; nt++) {
                    asm volatile(
                        "mma.sync.aligned.m16n8k16.row.col.f32.bf16.bf16.f32 "
                        "{%0,%1,%2,%3}, {%4,%5,%6,%7}, {%8,%9}, {%0,%1,%2,%3};"
                        : "+f"(acc[mt][nt][0]), "+f"(acc[mt][nt][1]),
                          "+f"(acc[mt][nt][2]), "+f"(acc[mt][nt][3])
                        : "r"(a[mt][0]), "r"(a[mt][1]), "r"(a[mt][2]), "r"(a[mt][3]),
                          "r"(bh[nt][0]), "r"(bh[nt][1]));
                }
        }
        __syncthreads();
    }

    // epilogue: write fp32 result + fused att dot products
    const int group = lane >> 2;
    const int tg    = lane & 3;

    float as0[4], as1[4], ad0[4], ad1[4];
#pragma unroll
    for (int nt = 0; nt < 4; nt++) {
        int col = bcol + wn + nt * 8 + tg * 2;
        as0[nt] = att_src[col];  as1[nt] = att_src[col + 1];
        ad0[nt] = att_dst[col];  ad1[nt] = att_dst[col + 1];
    }

#pragma unroll
    for (int mt = 0; mt < 4; mt++) {
        int m0 = brow + wm + mt * 16 + group;
        float v0s = 0.f, v8s = 0.f, v0d = 0.f, v8d = 0.f;
#pragma unroll
        for (int nt = 0; nt < 4; nt++) {
            int col = bcol + wn + nt * 8 + tg * 2;
            *(float2*)(g_h + (size_t)m0 * DIM + col) =
                make_float2(acc[mt][nt][0], acc[mt][nt][1]);
            *(float2*)(g_h + (size_t)(m0 + 8) * DIM + col) =
                make_float2(acc[mt][nt][2], acc[mt][nt][3]);
            v0s += acc[mt][nt][0] * as0[nt] + acc[mt][nt][1] * as1[nt];
            v8s += acc[mt][nt][2] * as0[nt] + acc[mt][nt][3] * as1[nt];
            v0d += acc[mt][nt][0] * ad0[nt] + acc[mt][nt][1] * ad1[nt];
            v8d += acc[mt][nt][2] * ad0[nt] + acc[mt][nt][3] * ad1[nt];
        }
#pragma unroll
        for (int o = 1; o <= 2; o <<= 1) {
            v0s += __shfl_xor_sync(0xffffffffu, v0s, o);
            v8s += __shfl_xor_sync(0xffffffffu, v8s, o);
            v0d += __shfl_xor_sync(0xffffffffu, v0d, o);
            v8d += __shfl_xor_sync(0xffffffffu, v8d, o);
        }
        if (tg == 0) {
            if (m0 < N_NODES) {
                atomicAdd(&g_as[m0], v0s);
                atomicAdd(&g_ad[m0], v0d);
            }
            if (m0 + 8 < N_NODES) {
                atomicAdd(&g_as[m0 + 8], v8s);
                atomicAdd(&g_ad[m0 + 8], v8d);
            }
        }
    }
}

__global__ void k_edge(const int* __restrict__ ei) {
    int j = blockIdx.x * blockDim.x + threadIdx.x;
    if (j >= ET) return;
    int src = (j < NE) ? ei[j]      : (j - NE);
    int dst = (j < NE) ? ei[NE + j] : (j - NE);
    float e = g_as[src] + g_ad[dst];
    e = (e >= 0.0f) ? e : 0.2f * e;                 // LeakyReLU(0.2)
    g_e[j] = e;
    atomicMax(&g_m[dst], enc_f(e));
    atomicAdd(&g_cnt[dst], 1);
}

__global__ void k_scan() {
    __shared__ int sh[1024];
    int tid = threadIdx.x;
    int carry = 0;
    for (int base = 0; base < N_NODES; base += 1024) {
        int i = base + tid;
        int v = (i < N_NODES) ? g_cnt[i] : 0;
        sh[tid] = v;
        __syncthreads();
        for (int ofs = 1; ofs < 1024; ofs <<= 1) {
            int t = (tid >= ofs) ? sh[tid - ofs] : 0;
            __syncthreads();
            sh[tid] += t;
            __syncthreads();
        }
        int incl = sh[tid];
        if (i < N_NODES) {
            int ex = carry + incl - v;
            g_off[i] = ex;
            g_cur[i] = ex;
        }
        carry += sh[1023];
        __syncthreads();
    }
    if (tid == 0) g_off[N_NODES] = carry;
}

// softmax numerators + CSR fill + attention dropout (threefry once per edge)
__global__ void k_fill(const int* __restrict__ ei) {
    int j = blockIdx.x * blockDim.x + threadIdx.x;
    if (j >= ET) return;
    int dst = (j < NE) ? ei[NE + j] : (j - NE);
    float m  = dec_f(g_m[dst]);
    float ee = __expf(g_e[j] - m);
    atomicAdd(&g_s[dst], ee);
    int pos = atomicAdd(&g_cur[dst], 1);
    g_csr[pos] = j;
    unsigned bits = tf_bits(KATT.a, KATT.b, (unsigned)j);
    float u = __uint_as_float((bits >> 9) | 0x3f800000u) - 1.0f;
    g_ee[j] = (u < 0.4f) ? ee * 2.5f : 0.0f;        // keep prob 0.4, x1/0.4
}

// block per dst node; 128 threads x float4 = 512 cols
__global__ void __launch_bounds__(128) k_agg(
    const int* __restrict__ ei,
    const float* __restrict__ bias,
    float* __restrict__ out)
{
    int dst = blockIdx.x;
    int c   = threadIdx.x * 4;
    float inv = 1.0f / (g_s[dst] + 1e-16f);
    float4 acc = make_float4(0.f, 0.f, 0.f, 0.f);
    int beg = g_off[dst], end = g_off[dst + 1];
    for (int p = beg; p < end; p++) {
        int eid = g_csr[p];
        float a = g_ee[eid];
        if (a != 0.0f) {
            float w = a * inv;
            int src = (eid < NE) ? ei[eid] : (eid - NE);
            float4 hv = *(const float4*)(g_h + (size_t)src * DIM + c);
            acc.x = fmaf(w, hv.x, acc.x);
            acc.y = fmaf(w, hv.y, acc.y);
            acc.z = fmaf(w, hv.z, acc.z);
            acc.w = fmaf(w, hv.w, acc.w);
        }
    }
    float4 bv = *(const float4*)(bias + c);
    acc.x += bv.x; acc.y += bv.y; acc.z += bv.z; acc.w += bv.w;
    *(float4*)(out + (size_t)dst * DIM + c) = acc;
}

// column sums + total sum of squares (for PairNorm)
#define CM_ROWS 235
__global__ void __launch_bounds__(256) k_colmean(const float* __restrict__ out) {
    __shared__ double ssq_sh[256];
    int tid = threadIdx.x;
    int r0 = blockIdx.x * CM_ROWS;
    int r1 = min(N_NODES, r0 + CM_ROWS);
    float s1 = 0.0f, s2 = 0.0f;
    double ssq = 0.0;
    for (int r = r0; r < r1; r++) {
        float v1 = out[(size_t)r * DIM + tid];
        float v2 = out[(size_t)r * DIM + tid + 256];
        s1 += v1; s2 += v2;
        ssq += (double)v1 * v1 + (double)v2 * v2;
    }
    atomicAdd(&g_colsum[tid],       (double)s1);
    atomicAdd(&g_colsum[tid + 256], (double)s2);
    ssq_sh[tid] = ssq;
    __syncthreads();
    for (int o = 128; o > 0; o >>= 1) {
        if (tid < o) ssq_sh[tid] += ssq_sh[tid + o];
        __syncthreads();
    }
    if (tid == 0) atomicAdd(&g_sumsq, ssq_sh[0]);
}

__global__ void k_stats() {
    __shared__ double sh[512];
    int t = threadIdx.x;
    double mu = g_colsum[t] / (double)N_NODES;
    g_mu[t] = (float)mu;
    sh[t] = mu * mu;
    __syncthreads();
    for (int o = 256; o > 0; o >>= 1) {
        if (t < o) sh[t] += sh[t + o];
        __syncthreads();
    }
    if (t == 0) {
        double var = g_sumsq / (double)N_NODES - sh[0];
        g_inv = (float)(1.0 / sqrt(1e-6 + var));
    }
}

__global__ void k_final(float* __restrict__ out) {
    unsigned i = (blockIdx.x * blockDim.x + threadIdx.x) * 4;
    if (i >= (unsigned)(N_NODES * DIM)) return;
    float4 v  = *(const float4*)(out + i);
    float4 mu = *(const float4*)(g_mu + (i & (DIM - 1)));
    float inv = g_inv;
    v.x = fmaxf((v.x - mu.x) * inv, 0.0f);
    v.y = fmaxf((v.y - mu.y) * inv, 0.0f);
    v.z = fmaxf((v.z - mu.z) * inv, 0.0f);
    v.w = fmaxf((v.w - mu.w) * inv, 0.0f);
    *(float4*)(out + i) = v;
}

// ---------------- launch ----------------
extern "C" void kernel_launch(void* const* d_in, const int* in_sizes, int n_in,
                              void* d_out, int out_size)
{
    const float* x       = (const float*)d_in[0];
    const int*   ei      = (const int*)  d_in[1];
    const float* W       = (const float*)d_in[2];
    const float* att_src = (const float*)d_in[3];
    const float* att_dst = (const float*)d_in[4];
    const float* bias    = (const float*)d_in[5];
    float*       out     = (float*)d_out;
    (void)in_sizes; (void)n_in; (void)out_size;

    cudaFuncSetAttribute(k_gemm_mma,
                         cudaFuncAttributeMaxDynamicSharedMemorySize, SM_GEMM);

    k_init<<<(N_NODES + 255) / 256, 256>>>();
    k_prep_a<<<(NPADD / 4 + 255) / 256, 256>>>(x);
    k_prep_w<<<(DIM * DIM + 255) / 256, 256>>>(W);
    k_gemm_mma<<<dim3(4, 235), 256, SM_GEMM>>>(att_src, att_dst);
    k_edge<<<(ET + 255) / 256, 256>>>(ei);
    k_scan<<<1, 1024>>>();
    k_fill<<<(ET + 255) / 256, 256>>>(ei);
    k_agg<<<N_NODES, 128>>>(ei, bias, out);
    k_colmean<<<(N_NODES + CM_ROWS - 1) / CM_ROWS, 256>>>(out);
    k_stats<<<1, 512>>>();
    k_final<<<(N_NODES * DIM / 4 + 255) / 256, 256>>>(out);
}

// round 11
// speedup vs baseline: 1.1553x; 1.0473x over previous
#include <cuda_runtime.h>
#include <cuda_bf16.h>
#include <math.h>
#include <stdint.h>

#define N_NODES 30000
#define DIM     512
#define NE      300000
#define ET      (NE + N_NODES)     // 330000 edges incl self-loops
#define MPAD    30080              // 235 * 128
#define NPADD   (MPAD * DIM)

// ---------------- scratch (static __device__, no allocations) ----------------
__device__ __nv_bfloat16 g_ah[NPADD];       // A hi (dropout applied)
__device__ __nv_bfloat16 g_al[NPADD];       // A lo
__device__ __nv_bfloat16 g_wh[DIM * DIM];   // W^T hi  [n, k]
__device__ __nv_bfloat16 g_wl[DIM * DIM];   // W^T lo
__device__ float    g_h[NPADD];
__device__ float    g_as[N_NODES];
__device__ float    g_ad[N_NODES];
__device__ float    g_e[ET];
__device__ float    g_ee[ET];               // after fill: masked ee * 2.5
__device__ unsigned g_m[N_NODES];           // encoded float max
__device__ float    g_s[N_NODES];
__device__ int      g_cnt[N_NODES];
__device__ int      g_off[N_NODES + 1];
__device__ int      g_cur[N_NODES];
__device__ int      g_csr[ET];
__device__ double   g_colsum[DIM];
__device__ double   g_sumsq;
__device__ float    g_mu[DIM];
__device__ float    g_inv;

// ---------------- threefry2x32 (JAX-exact, 20 rounds), constexpr-capable ----
__host__ __device__ constexpr unsigned rotl32(unsigned v, int d) {
    return (v << d) | (v >> (32 - d));
}

struct U2 { unsigned a, b; };

__host__ __device__ constexpr U2 threefry2x32(
    unsigned k0, unsigned k1, unsigned c0, unsigned c1)
{
    unsigned ks0 = k0, ks1 = k1, ks2 = k0 ^ k1 ^ 0x1BD11BDAu;
    unsigned x0 = c0 + ks0;
    unsigned x1 = c1 + ks1;

#define TF_R4(a,b,c,d) \
    x0 += x1; x1 = rotl32(x1, a); x1 ^= x0; \
    x0 += x1; x1 = rotl32(x1, b); x1 ^= x0; \
    x0 += x1; x1 = rotl32(x1, c); x1 ^= x0; \
    x0 += x1; x1 = rotl32(x1, d); x1 ^= x0;

    TF_R4(13,15,26,6)   x0 += ks1; x1 += ks2 + 1u;
    TF_R4(17,29,16,24)  x0 += ks2; x1 += ks0 + 2u;
    TF_R4(13,15,26,6)   x0 += ks0; x1 += ks1 + 3u;
    TF_R4(17,29,16,24)  x0 += ks1; x1 += ks2 + 4u;
    TF_R4(13,15,26,6)   x0 += ks2; x1 += ks0 + 5u;
#undef TF_R4
    return U2{x0, x1};
}

constexpr U2 KFEAT = threefry2x32(0u, 42u, 0u, 0u);
constexpr U2 KATT  = threefry2x32(0u, 42u, 0u, 1u);

__device__ __forceinline__ unsigned tf_bits(unsigned k0, unsigned k1, unsigned idx) {
    U2 r = threefry2x32(k0, k1, 0u, idx);
    return r.a ^ r.b;
}

// ---------------- float max encoding for atomicMax ----------------
__device__ __forceinline__ unsigned enc_f(float f) {
    unsigned u = __float_as_uint(f);
    return (u & 0x80000000u) ? ~u : (u | 0x80000000u);
}
__device__ __forceinline__ float dec_f(unsigned k) {
    unsigned u = (k & 0x80000000u) ? (k ^ 0x80000000u) : ~k;
    return __uint_as_float(u);
}

__device__ __forceinline__ uint32_t smem_u32(const void* p) {
    uint32_t a;
    asm("{ .reg .u64 t; cvta.to.shared.u64 t, %1; cvt.u32.u64 %0, t; }"
        : "=r"(a) : "l"(p));
    return a;
}
__device__ __forceinline__ void cp16(uint32_t dst, const void* src) {
    asm volatile("cp.async.cg.shared.global [%0], [%1], 16;"
                 :: "r"(dst), "l"(src) : "memory");
}

// ---------------- kernels ----------------
__global__ void k_init() {
    int i = blockIdx.x * blockDim.x + threadIdx.x;
    if (i < N_NODES) {
        g_cnt[i] = 0; g_s[i] = 0.0f; g_m[i] = 0u;
        g_as[i] = 0.0f; g_ad[i] = 0.0f;
    }
    if (i < DIM)     { g_colsum[i] = 0.0; }
    if (i == 0)      { g_sumsq = 0.0; }
}

// fused feature-dropout + bf16 hi/lo split, 4 elems/thread (ILP on threefry)
__global__ void k_prep_a(const float* __restrict__ x) {
    unsigned t  = blockIdx.x * blockDim.x + threadIdx.x;
    unsigned i0 = t * 4;
    if (i0 >= (unsigned)NPADD) return;

    unsigned hh[2] = {0u, 0u}, ll[2] = {0u, 0u};
    if (i0 < (unsigned)(N_NODES * DIM)) {       // region is 4-divisible
        float4 xv = *(const float4*)(x + i0);
        float vs[4] = {xv.x, xv.y, xv.z, xv.w};
        unsigned mb[4];
#pragma unroll
        for (int j = 0; j < 4; j++) mb[j] = tf_bits(KFEAT.a, KFEAT.b, i0 + j);
#pragma unroll
        for (int j = 0; j < 4; j++) {
            // keep  <=>  u < 0.5  <=>  top bit of bits is 0
            float v = (mb[j] & 0x80000000u) ? 0.0f : vs[j] * 2.0f;
            __nv_bfloat16 h = __float2bfloat16(v);
            __nv_bfloat16 l = __float2bfloat16(v - __bfloat162float(h));
            unsigned hu = (unsigned)__bfloat16_as_ushort(h);
            unsigned lu = (unsigned)__bfloat16_as_ushort(l);
            hh[j >> 1] |= hu << ((j & 1) * 16);
            ll[j >> 1] |= lu << ((j & 1) * 16);
        }
    }
    *(uint2*)((unsigned short*)g_ah + i0) = make_uint2(hh[0], hh[1]);
    *(uint2*)((unsigned short*)g_al + i0) = make_uint2(ll[0], ll[1]);
}

// transpose + bf16 hi/lo split of W:  g_w*[n*512+k] = split(W[k*512+n])
__global__ void k_prep_w(const float* __restrict__ W) {
    int i = blockIdx.x * blockDim.x + threadIdx.x;
    if (i >= DIM * DIM) return;
    int n = i >> 9, k = i & (DIM - 1);
    float v = W[k * DIM + n];
    __nv_bfloat16 h = __float2bfloat16(v);
    g_wh[i] = h;
    g_wl[i] = __float2bfloat16(v - __bfloat162float(h));
}

// ---------------- mma.sync bf16 GEMM, single-loop 3-product -----------------
// CTA tile 128x128, 8 warps (2x4), warp tile 64x32, BK=32.
// Per K-chunk load Ah,Al,Wh,Wl once; acc += ah*wh + ah*wl + al*wh.
// Fused epilogue: h row-dots with att_src/att_dst -> g_as/g_ad (atomic).
#define LDT 40                      // padded smem lead dim (bf16 elems)
#define GBK 32
#define NCH (DIM / GBK)             // 16 chunks
#define TILE_B (128 * LDT * 2)      // 10240 B per tile
#define STG_B  (4 * TILE_B)         // Ah,Al,Bh,Bl per stage = 40960 B
#define SM_GEMM (2 * STG_B)         // 81920 B

__global__ void __launch_bounds__(256, 2) k_gemm_mma(
    const float* __restrict__ att_src,
    const float* __restrict__ att_dst)
{
    extern __shared__ char smem[];

    const int tid  = threadIdx.x;
    const int wid  = tid >> 5;
    const int lane = tid & 31;
    const int brow = blockIdx.y * 128;
    const int bcol = blockIdx.x * 128;
    const int wm   = (wid >> 2) * 64;
    const int wn   = (wid & 3) * 32;

    const int lr = tid >> 2;              // 0..63 (x2 -> 128 rows)
    const int lc = (tid & 3) * 8;         // bf16 col group

    const uint32_t s0 = smem_u32(smem);

    float acc[4][4][4];
#pragma unroll
    for (int mt = 0; mt < 4; mt++)
#pragma unroll
        for (int nt = 0; nt < 4; nt++)
#pragma unroll
            for (int c = 0; c < 4; c++) acc[mt][nt][c] = 0.0f;

    const int a_row  = wm + (lane & 15);
    const int a_koff = (lane >> 4) * 8;
    const int b_row  = wn + (lane & 15);

    auto load_chunk = [&](int c, int st) {
        int k0 = c * GBK;
        uint32_t base = s0 + st * STG_B;
#pragma unroll
        for (int it = 0; it < 2; it++) {
            int r = lr + it * 64;
            uint32_t off = (r * LDT + lc) * 2;
            size_t ga = (size_t)(brow + r) * DIM + k0 + lc;
            size_t gb = (size_t)(bcol + r) * DIM + k0 + lc;
            cp16(base + 0 * TILE_B + off, g_ah + ga);
            cp16(base + 1 * TILE_B + off, g_al + ga);
            cp16(base + 2 * TILE_B + off, g_wh + gb);
            cp16(base + 3 * TILE_B + off, g_wl + gb);
        }
    };

    load_chunk(0, 0);
    asm volatile("cp.async.commit_group;" ::: "memory");

    for (int c = 0; c < NCH; c++) {
        int st = c & 1;
        if (c + 1 < NCH) {
            asm volatile("cp.async.wait_group 0;" ::: "memory");
            __syncthreads();
            load_chunk(c + 1, st ^ 1);
            asm volatile("cp.async.commit_group;" ::: "memory");
        } else {
            asm volatile("cp.async.wait_group 0;" ::: "memory");
            __syncthreads();
        }

        const __nv_bfloat16* Ah = (const __nv_bfloat16*)(smem + st * STG_B);
        const __nv_bfloat16* Al = (const __nv_bfloat16*)(smem + st * STG_B + TILE_B);
        const __nv_bfloat16* Bh = (const __nv_bfloat16*)(smem + st * STG_B + 2 * TILE_B);
        const __nv_bfloat16* Bl = (const __nv_bfloat16*)(smem + st * STG_B + 3 * TILE_B);

#pragma unroll
        for (int ks = 0; ks < 2; ks++) {
            int k16 = ks * 16;
            // B operands (resident for the whole k16 slice)
            uint32_t bh[4][2], bl[4][2];
#pragma unroll
            for (int nt2 = 0; nt2 < 2; nt2++) {
                uint32_t r0, r1, r2, r3;
                uint32_t addr = smem_u32(&Bh[(b_row + nt2 * 16) * LDT + k16 + a_koff]);
                asm volatile(
                    "ldmatrix.sync.aligned.m8n8.x4.shared.b16 {%0,%1,%2,%3}, [%4];"
                    : "=r"(r0), "=r"(r1), "=r"(r2), "=r"(r3) : "r"(addr));
                bh[2 * nt2][0] = r0; bh[2 * nt2 + 1][0] = r1;
                bh[2 * nt2][1] = r2; bh[2 * nt2 + 1][1] = r3;
                addr = smem_u32(&Bl[(b_row + nt2 * 16) * LDT + k16 + a_koff]);
                asm volatile(
                    "ldmatrix.sync.aligned.m8n8.x4.shared.b16 {%0,%1,%2,%3}, [%4];"
                    : "=r"(r0), "=r"(r1), "=r"(r2), "=r"(r3) : "r"(addr));
                bl[2 * nt2][0] = r0; bl[2 * nt2 + 1][0] = r1;
                bl[2 * nt2][1] = r2; bl[2 * nt2 + 1][1] = r3;
            }
            // A-high: two products
            uint32_t a[4][4];
#pragma unroll
            for (int mt = 0; mt < 4; mt++) {
                uint32_t addr = smem_u32(&Ah[(a_row + mt * 16) * LDT + k16 + a_koff]);
                asm volatile(
                    "ldmatrix.sync.aligned.m8n8.x4.shared.b16 {%0,%1,%2,%3}, [%4];"
                    : "=r"(a[mt][0]), "=r"(a[mt][1]), "=r"(a[mt][2]), "=r"(a[mt][3])
                    : "r"(addr));
            }
#pragma unroll
            for (int mt = 0; mt < 4; mt++)
#pragma unroll
                for (int nt = 0; nt < 4; nt++) {
                    asm volatile(
                        "mma.sync.aligned.m16n8k16.row.col.f32.bf16.bf16.f32 "
                        "{%0,%1,%2,%3}, {%4,%5,%6,%7}, {%8,%9}, {%0,%1,%2,%3};"
                        : "+f"(acc[mt][nt][0]), "+f"(acc[mt][nt][1]),
                          "+f"(acc[mt][nt][2]), "+f"(acc[mt][nt][3])
                        : "r"(a[mt][0]), "r"(a[mt][1]), "r"(a[mt][2]), "r"(a[mt][3]),
                          "r"(bh[nt][0]), "r"(bh[nt][1]));
                    asm volatile(
                        "mma.sync.aligned.m16n8k16.row.col.f32.bf16.bf16.f32 "
                        "{%0,%1,%2,%3}, {%4,%5,%6,%7}, {%8,%9}, {%0,%1,%2,%3};"
                        : "+f"(acc[mt][nt][0]), "+f"(acc[mt][nt][1]),
                          "+f"(acc[mt][nt][2]), "+f"(acc[mt][nt][3])
                        : "r"(a[mt][0]), "r"(a[mt][1]), "r"(a[mt][2]), "r"(a[mt][3]),
                          "r"(bl[nt][0]), "r"(bl[nt][1]));
                }
            // A-low: one product (reuse a regs)
#pragma unroll
            for (int mt = 0; mt < 4; mt++) {
                uint32_t addr = smem_u32(&Al[(a_row + mt * 16) * LDT + k16 + a_koff]);
                asm volatile(
                    "ldmatrix.sync.aligned.m8n8.x4.shared.b16 {%0,%1,%2,%3}, [%4];"
                    : "=r"(a[mt][0]), "=r"(a[mt][1]), "=r"(a[mt][2]), "=r"(a[mt][3])
                    : "r"(addr));
            }
#pragma unroll
            for (int mt = 0; mt < 4; mt++)
#pragma unroll
                for (int nt = 0; nt < 4; nt++) {
                    asm volatile(
                        "mma.sync.aligned.m16n8k16.row.col.f32.bf16.bf16.f32 "
                        "{%0,%1,%2,%3}, {%4,%5,%6,%7}, {%8,%9}, {%0,%1,%2,%3};"
                        : "+f"(acc[mt][nt][0]), "+f"(acc[mt][nt][1]),
                          "+f"(acc[mt][nt][2]), "+f"(acc[mt][nt][3])
                        : "r"(a[mt][0]), "r"(a[mt][1]), "r"(a[mt][2]), "r"(a[mt][3]),
                          "r"(bh[nt][0]), "r"(bh[nt][1]));
                }
        }
        if (c + 1 < NCH) __syncthreads();   // all warps done with stage st^1 reads? no:
        // NOTE: barrier here orders "all warps finished reading stage st" before the
        // NEXT iteration's cp.async writes into it (top barrier only orders arrival).
    }

    // epilogue: write fp32 result + fused att dot products
    const int group = lane >> 2;
    const int tg    = lane & 3;

    float as0[4], as1[4], ad0[4], ad1[4];
#pragma unroll
    for (int nt = 0; nt < 4; nt++) {
        int col = bcol + wn + nt * 8 + tg * 2;
        as0[nt] = att_src[col];  as1[nt] = att_src[col + 1];
        ad0[nt] = att_dst[col];  ad1[nt] = att_dst[col + 1];
    }

#pragma unroll
    for (int mt = 0; mt < 4; mt++) {
        int m0 = brow + wm + mt * 16 + group;
        float v0s = 0.f, v8s = 0.f, v0d = 0.f, v8d = 0.f;
#pragma unroll
        for (int nt = 0; nt < 4; nt++) {
            int col = bcol + wn + nt * 8 + tg * 2;
            *(float2*)(g_h + (size_t)m0 * DIM + col) =
                make_float2(acc[mt][nt][0], acc[mt][nt][1]);
            *(float2*)(g_h + (size_t)(m0 + 8) * DIM + col) =
                make_float2(acc[mt][nt][2], acc[mt][nt][3]);
            v0s += acc[mt][nt][0] * as0[nt] + acc[mt][nt][1] * as1[nt];
            v8s += acc[mt][nt][2] * as0[nt] + acc[mt][nt][3] * as1[nt];
            v0d += acc[mt][nt][0] * ad0[nt] + acc[mt][nt][1] * ad1[nt];
            v8d += acc[mt][nt][2] * ad0[nt] + acc[mt][nt][3] * ad1[nt];
        }
#pragma unroll
        for (int o = 1; o <= 2; o <<= 1) {
            v0s += __shfl_xor_sync(0xffffffffu, v0s, o);
            v8s += __shfl_xor_sync(0xffffffffu, v8s, o);
            v0d += __shfl_xor_sync(0xffffffffu, v0d, o);
            v8d += __shfl_xor_sync(0xffffffffu, v8d, o);
        }
        if (tg == 0) {
            if (m0 < N_NODES) {
                atomicAdd(&g_as[m0], v0s);
                atomicAdd(&g_ad[m0], v0d);
            }
            if (m0 + 8 < N_NODES) {
                atomicAdd(&g_as[m0 + 8], v8s);
                atomicAdd(&g_ad[m0 + 8], v8d);
            }
        }
    }
}

__global__ void k_edge(const int* __restrict__ ei) {
    int j = blockIdx.x * blockDim.x + threadIdx.x;
    if (j >= ET) return;
    int src = (j < NE) ? ei[j]      : (j - NE);
    int dst = (j < NE) ? ei[NE + j] : (j - NE);
    float e = g_as[src] + g_ad[dst];
    e = (e >= 0.0f) ? e : 0.2f * e;                 // LeakyReLU(0.2)
    g_e[j] = e;
    atomicMax(&g_m[dst], enc_f(e));
    atomicAdd(&g_cnt[dst], 1);
}

// warp-shuffle block scan: 3 barriers per 1024-element step (vs 20 before)
__global__ void k_scan() {
    __shared__ int wsum[32];
    __shared__ int wtot;
    int tid  = threadIdx.x;
    int lane = tid & 31;
    int wq   = tid >> 5;
    int carry = 0;
    for (int base = 0; base < N_NODES; base += 1024) {
        int i = base + tid;
        int v = (i < N_NODES) ? g_cnt[i] : 0;
        int incl = v;
#pragma unroll
        for (int o = 1; o < 32; o <<= 1) {
            int t = __shfl_up_sync(0xffffffffu, incl, o);
            if (lane >= o) incl += t;
        }
        if (lane == 31) wsum[wq] = incl;
        __syncthreads();
        if (wq == 0) {
            int s = wsum[lane];
#pragma unroll
            for (int o = 1; o < 32; o <<= 1) {
                int t = __shfl_up_sync(0xffffffffu, s, o);
                if (lane >= o) s += t;
            }
            wsum[lane] = s;                    // inclusive over warps
            if (lane == 31) wtot = s;
        }
        __syncthreads();
        int woff = (wq > 0) ? wsum[wq - 1] : 0;
        if (i < N_NODES) {
            int ex = carry + woff + incl - v;
            g_off[i] = ex;
            g_cur[i] = ex;
        }
        carry += wtot;
        __syncthreads();                       // protect wsum/wtot reuse
    }
    if (tid == 0) g_off[N_NODES] = carry;
}

// softmax numerators + CSR fill + attention dropout (threefry once per edge)
__global__ void k_fill(const int* __restrict__ ei) {
    int j = blockIdx.x * blockDim.x + threadIdx.x;
    if (j >= ET) return;
    int dst = (j < NE) ? ei[NE + j] : (j - NE);
    float m  = dec_f(g_m[dst]);
    float ee = __expf(g_e[j] - m);
    atomicAdd(&g_s[dst], ee);
    int pos = atomicAdd(&g_cur[dst], 1);
    g_csr[pos] = j;
    unsigned bits = tf_bits(KATT.a, KATT.b, (unsigned)j);
    float u = __uint_as_float((bits >> 9) | 0x3f800000u) - 1.0f;
    g_ee[j] = (u < 0.4f) ? ee * 2.5f : 0.0f;        // keep prob 0.4, x1/0.4
}

// block per dst node; 128 threads x float4 = 512 cols
__global__ void __launch_bounds__(128) k_agg(
    const int* __restrict__ ei,
    const float* __restrict__ bias,
    float* __restrict__ out)
{
    int dst = blockIdx.x;
    int c   = threadIdx.x * 4;
    float inv = 1.0f / (g_s[dst] + 1e-16f);
    float4 acc = make_float4(0.f, 0.f, 0.f, 0.f);
    int beg = g_off[dst], end = g_off[dst + 1];
    for (int p = beg; p < end; p++) {
        int eid = g_csr[p];
        float a = g_ee[eid];
        if (a != 0.0f) {
            float w = a * inv;
            int src = (eid < NE) ? ei[eid] : (eid - NE);
            float4 hv = *(const float4*)(g_h + (size_t)src * DIM + c);
            acc.x = fmaf(w, hv.x, acc.x);
            acc.y = fmaf(w, hv.y, acc.y);
            acc.z = fmaf(w, hv.z, acc.z);
            acc.w = fmaf(w, hv.w, acc.w);
        }
    }
    float4 bv = *(const float4*)(bias + c);
    acc.x += bv.x; acc.y += bv.y; acc.z += bv.z; acc.w += bv.w;
    *(float4*)(out + (size_t)dst * DIM + c) = acc;
}

// column sums + total sum of squares (for PairNorm)
#define CM_ROWS 235
__global__ void __launch_bounds__(256) k_colmean(const float* __restrict__ out) {
    __shared__ double ssq_sh[256];
    int tid = threadIdx.x;
    int r0 = blockIdx.x * CM_ROWS;
    int r1 = min(N_NODES, r0 + CM_ROWS);
    float s1 = 0.0f, s2 = 0.0f;
    double ssq = 0.0;
    for (int r = r0; r < r1; r++) {
        float v1 = out[(size_t)r * DIM + tid];
        float v2 = out[(size_t)r * DIM + tid + 256];
        s1 += v1; s2 += v2;
        ssq += (double)v1 * v1 + (double)v2 * v2;
    }
    atomicAdd(&g_colsum[tid],       (double)s1);
    atomicAdd(&g_colsum[tid + 256], (double)s2);
    ssq_sh[tid] = ssq;
    __syncthreads();
    for (int o = 128; o > 0; o >>= 1) {
        if (tid < o) ssq_sh[tid] += ssq_sh[tid + o];
        __syncthreads();
    }
    if (tid == 0) atomicAdd(&g_sumsq, ssq_sh[0]);
}

__global__ void k_stats() {
    __shared__ double sh[512];
    int t = threadIdx.x;
    double mu = g_colsum[t] / (double)N_NODES;
    g_mu[t] = (float)mu;
    sh[t] = mu * mu;
    __syncthreads();
    for (int o = 256; o > 0; o >>= 1) {
        if (t < o) sh[t] += sh[t + o];
        __syncthreads();
    }
    if (t == 0) {
        double var = g_sumsq / (double)N_NODES - sh[0];
        g_inv = (float)(1.0 / sqrt(1e-6 + var));
    }
}

__global__ void k_final(float* __restrict__ out) {
    unsigned i = (blockIdx.x * blockDim.x + threadIdx.x) * 4;
    if (i >= (unsigned)(N_NODES * DIM)) return;
    float4 v  = *(const float4*)(out + i);
    float4 mu = *(const float4*)(g_mu + (i & (DIM - 1)));
    float inv = g_inv;
    v.x = fmaxf((v.x - mu.x) * inv, 0.0f);
    v.y = fmaxf((v.y - mu.y) * inv, 0.0f);
    v.z = fmaxf((v.z - mu.z) * inv, 0.0f);
    v.w = fmaxf((v.w - mu.w) * inv, 0.0f);
    *(float4*)(out + i) = v;
}

// ---------------- launch ----------------
extern "C" void kernel_launch(void* const* d_in, const int* in_sizes, int n_in,
                              void* d_out, int out_size)
{
    const float* x       = (const float*)d_in[0];
    const int*   ei      = (const int*)  d_in[1];
    const float* W       = (const float*)d_in[2];
    const float* att_src = (const float*)d_in[3];
    const float* att_dst = (const float*)d_in[4];
    const float* bias    = (const float*)d_in[5];
    float*       out     = (float*)d_out;
    (void)in_sizes; (void)n_in; (void)out_size;

    cudaFuncSetAttribute(k_gemm_mma,
                         cudaFuncAttributeMaxDynamicSharedMemorySize, SM_GEMM);

    k_init<<<(N_NODES + 255) / 256, 256>>>();
    k_prep_a<<<(NPADD / 4 + 255) / 256, 256>>>(x);
    k_prep_w<<<(DIM * DIM + 255) / 256, 256>>>(W);
    k_gemm_mma<<<dim3(4, 235), 256, SM_GEMM>>>(att_src, att_dst);
    k_edge<<<(ET + 255) / 256, 256>>>(ei);
    k_scan<<<1, 1024>>>();
    k_fill<<<(ET + 255) / 256, 256>>>(ei);
    k_agg<<<N_NODES, 128>>>(ei, bias, out);
    k_colmean<<<(N_NODES + CM_ROWS - 1) / CM_ROWS, 256>>>(out);
    k_stats<<<1, 512>>>();
    k_final<<<(N_NODES * DIM / 4 + 255) / 256, 256>>>(out);
}

// round 12
// speedup vs baseline: 1.2958x; 1.1217x over previous
#include <cuda_runtime.h>
#include <cuda_bf16.h>
#include <math.h>
#include <stdint.h>

#define N_NODES 30000
#define DIM     512
#define NE      300000
#define ET      (NE + N_NODES)     // 330000 edges incl self-loops
#define MPAD    30080              // 235 * 128
#define NPADD   (MPAD * DIM)

// ---------------- scratch (static __device__, no allocations) ----------------
__device__ __nv_bfloat16 g_ah[NPADD];       // A hi (dropout applied)
__device__ __nv_bfloat16 g_al[NPADD];       // A lo
__device__ __nv_bfloat16 g_wh[DIM * DIM];   // W^T hi  [n, k]
__device__ __nv_bfloat16 g_wl[DIM * DIM];   // W^T lo
__device__ float    g_h[NPADD];
__device__ float    g_as[N_NODES];
__device__ float    g_ad[N_NODES];
__device__ float    g_e[ET];
__device__ float    g_s[N_NODES];
__device__ int      g_cnt[N_NODES];
__device__ int      g_off[N_NODES + 1];
__device__ int      g_cur[N_NODES];
__device__ int2     g_pay[ET];              // compacted: {src, ee*2.5f}
__device__ double   g_colsum[DIM];
__device__ double   g_sumsq;
__device__ float    g_mu[DIM];
__device__ float    g_inv;

// ---------------- threefry2x32 (JAX-exact, 20 rounds), constexpr-capable ----
__host__ __device__ constexpr unsigned rotl32(unsigned v, int d) {
    return (v << d) | (v >> (32 - d));
}

struct U2 { unsigned a, b; };

__host__ __device__ constexpr U2 threefry2x32(
    unsigned k0, unsigned k1, unsigned c0, unsigned c1)
{
    unsigned ks0 = k0, ks1 = k1, ks2 = k0 ^ k1 ^ 0x1BD11BDAu;
    unsigned x0 = c0 + ks0;
    unsigned x1 = c1 + ks1;

#define TF_R4(a,b,c,d) \
    x0 += x1; x1 = rotl32(x1, a); x1 ^= x0; \
    x0 += x1; x1 = rotl32(x1, b); x1 ^= x0; \
    x0 += x1; x1 = rotl32(x1, c); x1 ^= x0; \
    x0 += x1; x1 = rotl32(x1, d); x1 ^= x0;

    TF_R4(13,15,26,6)   x0 += ks1; x1 += ks2 + 1u;
    TF_R4(17,29,16,24)  x0 += ks2; x1 += ks0 + 2u;
    TF_R4(13,15,26,6)   x0 += ks0; x1 += ks1 + 3u;
    TF_R4(17,29,16,24)  x0 += ks1; x1 += ks2 + 4u;
    TF_R4(13,15,26,6)   x0 += ks2; x1 += ks0 + 5u;
#undef TF_R4
    return U2{x0, x1};
}

constexpr U2 KFEAT = threefry2x32(0u, 42u, 0u, 0u);
constexpr U2 KATT  = threefry2x32(0u, 42u, 0u, 1u);

__device__ __forceinline__ unsigned tf_bits(unsigned k0, unsigned k1, unsigned idx) {
    U2 r = threefry2x32(k0, k1, 0u, idx);
    return r.a ^ r.b;
}
// attention-dropout keep test (exact float compare as reference)
__device__ __forceinline__ bool att_keep(unsigned j) {
    unsigned bits = tf_bits(KATT.a, KATT.b, j);
    float u = __uint_as_float((bits >> 9) | 0x3f800000u) - 1.0f;
    return u < 0.4f;
}

__device__ __forceinline__ uint32_t smem_u32(const void* p) {
    uint32_t a;
    asm("{ .reg .u64 t; cvta.to.shared.u64 t, %1; cvt.u32.u64 %0, t; }"
        : "=r"(a) : "l"(p));
    return a;
}
__device__ __forceinline__ void cp16(uint32_t dst, const void* src) {
    asm volatile("cp.async.cg.shared.global [%0], [%1], 16;"
                 :: "r"(dst), "l"(src) : "memory");
}

// ---------------- kernels ----------------
// fused init + W transpose/split
__global__ void k_prep_w(const float* __restrict__ W) {
    int i = blockIdx.x * blockDim.x + threadIdx.x;
    if (i < DIM * DIM) {
        int n = i >> 9, k = i & (DIM - 1);
        float v = W[k * DIM + n];
        __nv_bfloat16 h = __float2bfloat16(v);
        g_wh[i] = h;
        g_wl[i] = __float2bfloat16(v - __bfloat162float(h));
    }
    if (i < N_NODES) {
        g_cnt[i] = 0; g_s[i] = 0.0f;
        g_as[i] = 0.0f; g_ad[i] = 0.0f;
    }
    if (i < DIM) { g_colsum[i] = 0.0; }
    if (i == 0)  { g_sumsq = 0.0; }
}

// fused feature-dropout + bf16 hi/lo split, 4 elems/thread (ILP on threefry)
__global__ void k_prep_a(const float* __restrict__ x) {
    unsigned t  = blockIdx.x * blockDim.x + threadIdx.x;
    unsigned i0 = t * 4;
    if (i0 >= (unsigned)NPADD) return;

    unsigned hh[2] = {0u, 0u}, ll[2] = {0u, 0u};
    if (i0 < (unsigned)(N_NODES * DIM)) {       // region is 4-divisible
        float4 xv = *(const float4*)(x + i0);
        float vs[4] = {xv.x, xv.y, xv.z, xv.w};
        unsigned mb[4];
#pragma unroll
        for (int j = 0; j < 4; j++) mb[j] = tf_bits(KFEAT.a, KFEAT.b, i0 + j);
#pragma unroll
        for (int j = 0; j < 4; j++) {
            // keep  <=>  u < 0.5  <=>  top bit of bits is 0
            float v = (mb[j] & 0x80000000u) ? 0.0f : vs[j] * 2.0f;
            __nv_bfloat16 h = __float2bfloat16(v);
            __nv_bfloat16 l = __float2bfloat16(v - __bfloat162float(h));
            unsigned hu = (unsigned)__bfloat16_as_ushort(h);
            unsigned lu = (unsigned)__bfloat16_as_ushort(l);
            hh[j >> 1] |= hu << ((j & 1) * 16);
            ll[j >> 1] |= lu << ((j & 1) * 16);
        }
    }
    *(uint2*)((unsigned short*)g_ah + i0) = make_uint2(hh[0], hh[1]);
    *(uint2*)((unsigned short*)g_al + i0) = make_uint2(ll[0], ll[1]);
}

// ---------------- mma.sync bf16 GEMM, single-loop 3-product -----------------
// CTA tile 128x128, 8 warps (2x4), warp tile 64x32, BK=32.
// Per K-chunk load Ah,Al,Wh,Wl once; acc += ah*wh + ah*wl + al*wh.
// Fused epilogue: h row-dots with att_src/att_dst -> g_as/g_ad (atomic).
#define LDT 40                      // padded smem lead dim (bf16 elems)
#define GBK 32
#define NCH (DIM / GBK)             // 16 chunks
#define TILE_B (128 * LDT * 2)      // 10240 B per tile
#define STG_B  (4 * TILE_B)         // Ah,Al,Bh,Bl per stage = 40960 B
#define SM_GEMM (2 * STG_B)         // 81920 B

__global__ void __launch_bounds__(256, 2) k_gemm_mma(
    const float* __restrict__ att_src,
    const float* __restrict__ att_dst)
{
    extern __shared__ char smem[];

    const int tid  = threadIdx.x;
    const int wid  = tid >> 5;
    const int lane = tid & 31;
    const int brow = blockIdx.y * 128;
    const int bcol = blockIdx.x * 128;
    const int wm   = (wid >> 2) * 64;
    const int wn   = (wid & 3) * 32;

    const int lr = tid >> 2;              // 0..63 (x2 -> 128 rows)
    const int lc = (tid & 3) * 8;         // bf16 col group

    const uint32_t s0 = smem_u32(smem);

    float acc[4][4][4];
#pragma unroll
    for (int mt = 0; mt < 4; mt++)
#pragma unroll
        for (int nt = 0; nt < 4; nt++)
#pragma unroll
            for (int c = 0; c < 4; c++) acc[mt][nt][c] = 0.0f;

    const int a_row  = wm + (lane & 15);
    const int a_koff = (lane >> 4) * 8;
    const int b_row  = wn + (lane & 15);

    auto load_chunk = [&](int c, int st) {
        int k0 = c * GBK;
        uint32_t base = s0 + st * STG_B;
#pragma unroll
        for (int it = 0; it < 2; it++) {
            int r = lr + it * 64;
            uint32_t off = (r * LDT + lc) * 2;
            size_t ga = (size_t)(brow + r) * DIM + k0 + lc;
            size_t gb = (size_t)(bcol + r) * DIM + k0 + lc;
            cp16(base + 0 * TILE_B + off, g_ah + ga);
            cp16(base + 1 * TILE_B + off, g_al + ga);
            cp16(base + 2 * TILE_B + off, g_wh + gb);
            cp16(base + 3 * TILE_B + off, g_wl + gb);
        }
    };

    load_chunk(0, 0);
    asm volatile("cp.async.commit_group;" ::: "memory");

    for (int c = 0; c < NCH; c++) {
        int st = c & 1;
        if (c + 1 < NCH) {
            asm volatile("cp.async.wait_group 0;" ::: "memory");
            __syncthreads();
            load_chunk(c + 1, st ^ 1);
            asm volatile("cp.async.commit_group;" ::: "memory");
        } else {
            asm volatile("cp.async.wait_group 0;" ::: "memory");
            __syncthreads();
        }

        const __nv_bfloat16* Ah = (const __nv_bfloat16*)(smem + st * STG_B);
        const __nv_bfloat16* Al = (const __nv_bfloat16*)(smem + st * STG_B + TILE_B);
        const __nv_bfloat16* Bh = (const __nv_bfloat16*)(smem + st * STG_B + 2 * TILE_B);
        const __nv_bfloat16* Bl = (const __nv_bfloat16*)(smem + st * STG_B + 3 * TILE_B);

#pragma unroll
        for (int ks = 0; ks < 2; ks++) {
            int k16 = ks * 16;
            uint32_t bh[4][2], bl[4][2];
#pragma unroll
            for (int nt2 = 0; nt2 < 2; nt2++) {
                uint32_t r0, r1, r2, r3;
                uint32_t addr = smem_u32(&Bh[(b_row + nt2 * 16) * LDT + k16 + a_koff]);
                asm volatile(
                    "ldmatrix.sync.aligned.m8n8.x4.shared.b16 {%0,%1,%2,%3}, [%4];"
                    : "=r"(r0), "=r"(r1), "=r"(r2), "=r"(r3) : "r"(addr));
                bh[2 * nt2][0] = r0; bh[2 * nt2 + 1][0] = r1;
                bh[2 * nt2][1] = r2; bh[2 * nt2 + 1][1] = r3;
                addr = smem_u32(&Bl[(b_row + nt2 * 16) * LDT + k16 + a_koff]);
                asm volatile(
                    "ldmatrix.sync.aligned.m8n8.x4.shared.b16 {%0,%1,%2,%3}, [%4];"
                    : "=r"(r0), "=r"(r1), "=r"(r2), "=r"(r3) : "r"(addr));
                bl[2 * nt2][0] = r0; bl[2 * nt2 + 1][0] = r1;
                bl[2 * nt2][1] = r2; bl[2 * nt2 + 1][1] = r3;
            }
            uint32_t a[4][4];
#pragma unroll
            for (int mt = 0; mt < 4; mt++) {
                uint32_t addr = smem_u32(&Ah[(a_row + mt * 16) * LDT + k16 + a_koff]);
                asm volatile(
                    "ldmatrix.sync.aligned.m8n8.x4.shared.b16 {%0,%1,%2,%3}, [%4];"
                    : "=r"(a[mt][0]), "=r"(a[mt][1]), "=r"(a[mt][2]), "=r"(a[mt][3])
                    : "r"(addr));
            }
#pragma unroll
            for (int mt = 0; mt < 4; mt++)
#pragma unroll
                for (int nt = 0; nt < 4; nt++) {
                    asm volatile(
                        "mma.sync.aligned.m16n8k16.row.col.f32.bf16.bf16.f32 "
                        "{%0,%1,%2,%3}, {%4,%5,%6,%7}, {%8,%9}, {%0,%1,%2,%3};"
                        : "+f"(acc[mt][nt][0]), "+f"(acc[mt][nt][1]),
                          "+f"(acc[mt][nt][2]), "+f"(acc[mt][nt][3])
                        : "r"(a[mt][0]), "r"(a[mt][1]), "r"(a[mt][2]), "r"(a[mt][3]),
                          "r"(bh[nt][0]), "r"(bh[nt][1]));
                    asm volatile(
                        "mma.sync.aligned.m16n8k16.row.col.f32.bf16.bf16.f32 "
                        "{%0,%1,%2,%3}, {%4,%5,%6,%7}, {%8,%9}, {%0,%1,%2,%3};"
                        : "+f"(acc[mt][nt][0]), "+f"(acc[mt][nt][1]),
                          "+f"(acc[mt][nt][2]), "+f"(acc[mt][nt][3])
                        : "r"(a[mt][0]), "r"(a[mt][1]), "r"(a[mt][2]), "r"(a[mt][3]),
                          "r"(bl[nt][0]), "r"(bl[nt][1]));
                }
#pragma unroll
            for (int mt = 0; mt < 4; mt++) {
                uint32_t addr = smem_u32(&Al[(a_row + mt * 16) * LDT + k16 + a_koff]);
                asm volatile(
                    "ldmatrix.sync.aligned.m8n8.x4.shared.b16 {%0,%1,%2,%3}, [%4];"
                    : "=r"(a[mt][0]), "=r"(a[mt][1]), "=r"(a[mt][2]), "=r"(a[mt][3])
                    : "r"(addr));
            }
#pragma unroll
            for (int mt = 0; mt < 4; mt++)
#pragma unroll
                for (int nt = 0; nt < 4; nt++) {
                    asm volatile(
                        "mma.sync.aligned.m16n8k16.row.col.f32.bf16.bf16.f32 "
                        "{%0,%1,%2,%3}, {%4,%5,%6,%7}, {%8,%9}, {%0,%1,%2,%3};"
                        : "+f"(acc[mt][nt][0]), "+f"(acc[mt][nt][1]),
                          "+f"(acc[mt][nt][2]), "+f"(acc[mt][nt][3])
                        : "r"(a[mt][0]), "r"(a[mt][1]), "r"(a[mt][2]), "r"(a[mt][3]),
                          "r"(bh[nt][0]), "r"(bh[nt][1]));
                }
        }
        if (c + 1 < NCH) __syncthreads();
        // barrier orders "all warps finished reading stage st" before the
        // NEXT iteration's cp.async writes into it.
    }

    // epilogue: write fp32 result + fused att dot products
    const int group = lane >> 2;
    const int tg    = lane & 3;

    float as0[4], as1[4], ad0[4], ad1[4];
#pragma unroll
    for (int nt = 0; nt < 4; nt++) {
        int col = bcol + wn + nt * 8 + tg * 2;
        as0[nt] = att_src[col];  as1[nt] = att_src[col + 1];
        ad0[nt] = att_dst[col];  ad1[nt] = att_dst[col + 1];
    }

#pragma unroll
    for (int mt = 0; mt < 4; mt++) {
        int m0 = brow + wm + mt * 16 + group;
        float v0s = 0.f, v8s = 0.f, v0d = 0.f, v8d = 0.f;
#pragma unroll
        for (int nt = 0; nt < 4; nt++) {
            int col = bcol + wn + nt * 8 + tg * 2;
            *(float2*)(g_h + (size_t)m0 * DIM + col) =
                make_float2(acc[mt][nt][0], acc[mt][nt][1]);
            *(float2*)(g_h + (size_t)(m0 + 8) * DIM + col) =
                make_float2(acc[mt][nt][2], acc[mt][nt][3]);
            v0s += acc[mt][nt][0] * as0[nt] + acc[mt][nt][1] * as1[nt];
            v8s += acc[mt][nt][2] * as0[nt] + acc[mt][nt][3] * as1[nt];
            v0d += acc[mt][nt][0] * ad0[nt] + acc[mt][nt][1] * ad1[nt];
            v8d += acc[mt][nt][2] * ad0[nt] + acc[mt][nt][3] * ad1[nt];
        }
#pragma unroll
        for (int o = 1; o <= 2; o <<= 1) {
            v0s += __shfl_xor_sync(0xffffffffu, v0s, o);
            v8s += __shfl_xor_sync(0xffffffffu, v8s, o);
            v0d += __shfl_xor_sync(0xffffffffu, v0d, o);
            v8d += __shfl_xor_sync(0xffffffffu, v8d, o);
        }
        if (tg == 0) {
            if (m0 < N_NODES) {
                atomicAdd(&g_as[m0], v0s);
                atomicAdd(&g_ad[m0], v0d);
            }
            if (m0 + 8 < N_NODES) {
                atomicAdd(&g_as[m0 + 8], v8s);
                atomicAdd(&g_ad[m0 + 8], v8d);
            }
        }
    }
}

// edge logits + kept-edge counts (no max pass; softmax is shift-invariant
// and |e| <~ 15 so exp() is safe in fp32)
__global__ void k_edge(const int* __restrict__ ei) {
    int j = blockIdx.x * blockDim.x + threadIdx.x;
    if (j >= ET) return;
    int src = (j < NE) ? ei[j]      : (j - NE);
    int dst = (j < NE) ? ei[NE + j] : (j - NE);
    float e = g_as[src] + g_ad[dst];
    e = (e >= 0.0f) ? e : 0.2f * e;                 // LeakyReLU(0.2)
    g_e[j] = e;
    if (att_keep((unsigned)j)) atomicAdd(&g_cnt[dst], 1);
}

// warp-shuffle block scan: 3 barriers per 1024-element step
__global__ void k_scan() {
    __shared__ int wsum[32];
    __shared__ int wtot;
    int tid  = threadIdx.x;
    int lane = tid & 31;
    int wq   = tid >> 5;
    int carry = 0;
    for (int base = 0; base < N_NODES; base += 1024) {
        int i = base + tid;
        int v = (i < N_NODES) ? g_cnt[i] : 0;
        int incl = v;
#pragma unroll
        for (int o = 1; o < 32; o <<= 1) {
            int t = __shfl_up_sync(0xffffffffu, incl, o);
            if (lane >= o) incl += t;
        }
        if (lane == 31) wsum[wq] = incl;
        __syncthreads();
        if (wq == 0) {
            int s = wsum[lane];
#pragma unroll
            for (int o = 1; o < 32; o <<= 1) {
                int t = __shfl_up_sync(0xffffffffu, s, o);
                if (lane >= o) s += t;
            }
            wsum[lane] = s;
            if (lane == 31) wtot = s;
        }
        __syncthreads();
        int woff = (wq > 0) ? wsum[wq - 1] : 0;
        if (i < N_NODES) {
            int ex = carry + woff + incl - v;
            g_off[i] = ex;
            g_cur[i] = ex;
        }
        carry += wtot;
        __syncthreads();
    }
    if (tid == 0) g_off[N_NODES] = carry;
}

// softmax numerators + compacted CSR fill (payload {src, ee*2.5} kept only)
__global__ void k_fill(const int* __restrict__ ei) {
    int j = blockIdx.x * blockDim.x + threadIdx.x;
    if (j >= ET) return;
    int dst = (j < NE) ? ei[NE + j] : (j - NE);
    float ee = __expf(g_e[j]);
    atomicAdd(&g_s[dst], ee);
    if (att_keep((unsigned)j)) {
        int src = (j < NE) ? ei[j] : (j - NE);
        int pos = atomicAdd(&g_cur[dst], 1);
        g_pay[pos] = make_int2(src, __float_as_int(ee * 2.5f));
    }
}

// block per dst node; 128 threads x float4 = 512 cols; branch-free
__global__ void __launch_bounds__(128) k_agg(
    const float* __restrict__ bias,
    float* __restrict__ out)
{
    int dst = blockIdx.x;
    int c   = threadIdx.x * 4;
    float inv = 1.0f / (g_s[dst] + 1e-16f);
    float4 acc = make_float4(0.f, 0.f, 0.f, 0.f);
    int beg = g_off[dst], end = g_off[dst + 1];
    for (int p = beg; p < end; p++) {
        int2 rec = g_pay[p];
        float w = __int_as_float(rec.y) * inv;
        float4 hv = *(const float4*)(g_h + (size_t)rec.x * DIM + c);
        acc.x = fmaf(w, hv.x, acc.x);
        acc.y = fmaf(w, hv.y, acc.y);
        acc.z = fmaf(w, hv.z, acc.z);
        acc.w = fmaf(w, hv.w, acc.w);
    }
    float4 bv = *(const float4*)(bias + c);
    acc.x += bv.x; acc.y += bv.y; acc.z += bv.z; acc.w += bv.w;
    *(float4*)(out + (size_t)dst * DIM + c) = acc;
}

// column sums + total sum of squares (for PairNorm)
#define CM_ROWS 235
__global__ void __launch_bounds__(256) k_colmean(const float* __restrict__ out) {
    __shared__ double ssq_sh[256];
    int tid = threadIdx.x;
    int r0 = blockIdx.x * CM_ROWS;
    int r1 = min(N_NODES, r0 + CM_ROWS);
    float s1 = 0.0f, s2 = 0.0f;
    double ssq = 0.0;
    for (int r = r0; r < r1; r++) {
        float v1 = out[(size_t)r * DIM + tid];
        float v2 = out[(size_t)r * DIM + tid + 256];
        s1 += v1; s2 += v2;
        ssq += (double)v1 * v1 + (double)v2 * v2;
    }
    atomicAdd(&g_colsum[tid],       (double)s1);
    atomicAdd(&g_colsum[tid + 256], (double)s2);
    ssq_sh[tid] = ssq;
    __syncthreads();
    for (int o = 128; o > 0; o >>= 1) {
        if (tid < o) ssq_sh[tid] += ssq_sh[tid + o];
        __syncthreads();
    }
    if (tid == 0) atomicAdd(&g_sumsq, ssq_sh[0]);
}

__global__ void k_stats() {
    __shared__ double sh[512];
    int t = threadIdx.x;
    double mu = g_colsum[t] / (double)N_NODES;
    g_mu[t] = (float)mu;
    sh[t] = mu * mu;
    __syncthreads();
    for (int o = 256; o > 0; o >>= 1) {
        if (t < o) sh[t] += sh[t + o];
        __syncthreads();
    }
    if (t == 0) {
        double var = g_sumsq / (double)N_NODES - sh[0];
        g_inv = (float)(1.0 / sqrt(1e-6 + var));
    }
}

__global__ void k_final(float* __restrict__ out) {
    unsigned i = (blockIdx.x * blockDim.x + threadIdx.x) * 4;
    if (i >= (unsigned)(N_NODES * DIM)) return;
    float4 v  = *(const float4*)(out + i);
    float4 mu = *(const float4*)(g_mu + (i & (DIM - 1)));
    float inv = g_inv;
    v.x = fmaxf((v.x - mu.x) * inv, 0.0f);
    v.y = fmaxf((v.y - mu.y) * inv, 0.0f);
    v.z = fmaxf((v.z - mu.z) * inv, 0.0f);
    v.w = fmaxf((v.w - mu.w) * inv, 0.0f);
    *(float4*)(out + i) = v;
}

// ---------------- launch ----------------
extern "C" void kernel_launch(void* const* d_in, const int* in_sizes, int n_in,
                              void* d_out, int out_size)
{
    const float* x       = (const float*)d_in[0];
    const int*   ei      = (const int*)  d_in[1];
    const float* W       = (const float*)d_in[2];
    const float* att_src = (const float*)d_in[3];
    const float* att_dst = (const float*)d_in[4];
    const float* bias    = (const float*)d_in[5];
    float*       out     = (float*)d_out;
    (void)in_sizes; (void)n_in; (void)out_size;

    cudaFuncSetAttribute(k_gemm_mma,
                         cudaFuncAttributeMaxDynamicSharedMemorySize, SM_GEMM);

    k_prep_w<<<(DIM * DIM + 255) / 256, 256>>>(W);
    k_prep_a<<<(NPADD / 4 + 255) / 256, 256>>>(x);
    k_gemm_mma<<<dim3(4, 235), 256, SM_GEMM>>>(att_src, att_dst);
    k_edge<<<(ET + 255) / 256, 256>>>(ei);
    k_scan<<<1, 1024>>>();
    k_fill<<<(ET + 255) / 256, 256>>>(ei);
    k_agg<<<N_NODES, 128>>>(bias, out);
    k_colmean<<<(N_NODES + CM_ROWS - 1) / CM_ROWS, 256>>>(out);
    k_stats<<<1, 512>>>();
    k_final<<<(N_NODES * DIM / 4 + 255) / 256, 256>>>(out);
}